// round 6
// baseline (speedup 1.0000x reference)
#include <cuda_runtime.h>
#include <cstdint>
#include <climits>

// out = self_tensor; out[sorted_index[i], :] += value[i, :]
// N=262144 rows, M=1048576 updates, D=128 cols, fp32. sorted_index SORTED,
// delivered as int32 by the harness.
//
// SINGLE fused kernel, value-centric, zero atomics:
//   warp w owns idx chunk [i0, i1) = [32w, 32w+32). One coalesced load puts
//   the chunk indices in registers; ballot(idx[l] != idx[l-1]) marks run
//   starts. The warp owns output rows (idx[i0-1], idx[i1-1]]:
//     - for each run starting in-chunk: out[b] = self[b] + sum(value[run])
//       (last run may extend past i1 -> short L2-hit scan of idx)
//     - rows in gaps between runs: out[r] = self[r] (untouched rows)
//     - last warp copies the tail (idx[M-1], N).
//   Runs partition value; gaps partition untouched rows -> minimal 776MB
//   traffic, one launch, no CSR scratch, no atomics. Streaming loads/stores
//   (__ldcs/__stcs) keep idx L2-resident.

static constexpr int D4 = 32;      // 128 floats = 32 float4/row
static constexpr int CHUNK = 32;   // idx entries per warp

__global__ void fused_scatter_add_kernel(const float* __restrict__ self_t,
                                         const float* __restrict__ value,
                                         const int* __restrict__ idx,
                                         float* __restrict__ out,
                                         int n_rows, int m) {
    const unsigned FULL = 0xffffffffu;
    const int warp = (blockIdx.x * blockDim.x + threadIdx.x) >> 5;
    const int lane = threadIdx.x & 31;

    const int i0 = warp * CHUNK;
    if (i0 >= m) return;
    const int i1 = (i0 + CHUNK < m) ? i0 + CHUNK : m;
    const int valid = i1 - i0;

    const float4* __restrict__ selfv = reinterpret_cast<const float4*>(self_t);
    const float4* __restrict__ valv  = reinterpret_cast<const float4*>(value);
    float4* __restrict__ outv        = reinterpret_cast<float4*>(out);

    // chunk indices into registers: lane l holds idx[i0+l]
    const int my = (i0 + lane < m) ? __ldg(&idx[i0 + lane]) : INT_MAX;
    // index just before the chunk (previous warp's last entry)
    const int a = (i0 > 0) ? __ldg(&idx[i0 - 1]) : -1;

    int left = __shfl_up_sync(FULL, my, 1);
    if (lane == 0) left = a;
    // bit l set <=> position i0+l starts a new run (and is in-bounds)
    unsigned mask = __ballot_sync(FULL, (my != left) && (lane < valid));

    int prev = a;
    unsigned rem = mask;
    while (rem) {
        const int p = __ffs(rem) - 1;
        rem &= rem - 1;
        const int b   = __shfl_sync(FULL, my, p);
        const int nxt = rem ? (__ffs(rem) - 1) : valid;

        // copy-only rows in the gap (prev, b)
        for (int r = prev + 1; r < b; ++r)
            __stcs(&outv[(size_t)r * D4 + lane],
                   __ldcs(&selfv[(size_t)r * D4 + lane]));

        // accumulate run of b: in-chunk part [i0+p, i0+nxt)
        float4 acc = __ldcs(&selfv[(size_t)b * D4 + lane]);
        const float4* pv = valv + (size_t)(i0 + p) * D4 + lane;
        int n = nxt - p;
        while (n >= 4) {
            float4 v0 = __ldcs(pv);
            float4 v1 = __ldcs(pv + D4);
            float4 v2 = __ldcs(pv + 2 * D4);
            float4 v3 = __ldcs(pv + 3 * D4);
            acc.x += v0.x; acc.y += v0.y; acc.z += v0.z; acc.w += v0.w;
            acc.x += v1.x; acc.y += v1.y; acc.z += v1.z; acc.w += v1.w;
            acc.x += v2.x; acc.y += v2.y; acc.z += v2.z; acc.w += v2.w;
            acc.x += v3.x; acc.y += v3.y; acc.z += v3.z; acc.w += v3.w;
            pv += 4 * D4; n -= 4;
        }
        if (n >= 2) {
            float4 v0 = __ldcs(pv);
            float4 v1 = __ldcs(pv + D4);
            acc.x += v0.x; acc.y += v0.y; acc.z += v0.z; acc.w += v0.w;
            acc.x += v1.x; acc.y += v1.y; acc.z += v1.z; acc.w += v1.w;
            pv += 2 * D4; n -= 2;
        }
        if (n) {
            float4 v = __ldcs(pv);
            acc.x += v.x; acc.y += v.y; acc.z += v.z; acc.w += v.w;
        }

        // last run in chunk may extend past i1
        if (nxt == valid) {
            int j = i1;
            while (j < m && __ldg(&idx[j]) == b) {
                float4 v = __ldcs(&valv[(size_t)j * D4 + lane]);
                acc.x += v.x; acc.y += v.y; acc.z += v.z; acc.w += v.w;
                ++j;
            }
        }

        __stcs(&outv[(size_t)b * D4 + lane], acc);
        prev = b;
    }

    // last warp copies the tail (idx[M-1], N)
    if (i1 == m) {
        for (int r = prev + 1; r < n_rows; ++r)
            __stcs(&outv[(size_t)r * D4 + lane],
                   __ldcs(&selfv[(size_t)r * D4 + lane]));
    }
}

extern "C" void kernel_launch(void* const* d_in, const int* in_sizes, int n_in,
                              void* d_out, int out_size) {
    const float* self_t = (const float*)d_in[0];  // (N, 128) fp32
    const float* value  = (const float*)d_in[1];  // (M, 128) fp32
    const int*   idx    = (const int*)d_in[2];    // (M,) sorted
    // d_in[3] = pos, unused

    const int m      = in_sizes[2];       // 1048576
    const int n_rows = out_size / 128;    // 262144

    const int warps   = (m + CHUNK - 1) / CHUNK;   // 32768
    const int threads = 256;                       // 8 warps/block
    const int blocks  = (warps * 32 + threads - 1) / threads;

    fused_scatter_add_kernel<<<blocks, threads>>>(self_t, value, idx,
                                                  (float*)d_out, n_rows, m);
}